// round 15
// baseline (speedup 1.0000x reference)
#include <cuda_runtime.h>
#include <cuda_fp16.h>
#include <stdint.h>
#include <math.h>

// Problem constants
#define BB 2
#define SS 2048
#define EE 1024
#define HH 16
#define DH 64
#define M_TOK (BB * SS)        // 4096
#define N_QKV (3 * EE)         // 3072

// Scratch (__device__ globals; no allocations allowed)
__device__ __half g_ah[M_TOK * EE];       // hidden, fp16
__device__ __half g_wqkvh[N_QKV * EE];    // Wqkv^T fp16 [3072,1024]
__device__ __half g_wprojh[EE * EE];      // Wproj^T fp16
__device__ __half g_qh[M_TOK * EE];       // Q fp16, pre-scaled by 0.125*log2e
__device__ __half g_kh[M_TOK * EE];       // K fp16
__device__ __half g_vh[M_TOK * EE];       // V fp16
__device__ __half g_ctxh[M_TOK * EE];     // attention output fp16
__device__ __half g_b2h[SS * SS];         // bias*log2e + BADD, fp16

// softmax folding: p = 2^( (qk/8)*log2e + bias*log2e + (5 - 4*log2e) )
#define QSCALE  (0.125f * 1.4426950408889634f)
#define BADD    (5.0f - 4.0f * 1.4426950408889634f)

// ---------------------------------------------------------------------------
// helpers
// ---------------------------------------------------------------------------
__device__ __forceinline__ void mma_fp16(float c[4], const unsigned a[4], const unsigned b[2]) {
    asm volatile(
        "mma.sync.aligned.m16n8k16.row.col.f32.f16.f16.f32 "
        "{%0,%1,%2,%3}, {%4,%5,%6,%7}, {%8,%9}, {%0,%1,%2,%3};"
        : "+f"(c[0]), "+f"(c[1]), "+f"(c[2]), "+f"(c[3])
        : "r"(a[0]), "r"(a[1]), "r"(a[2]), "r"(a[3]), "r"(b[0]), "r"(b[1]));
}

__device__ __forceinline__ unsigned pack_h2(float lo, float hi) {
    __half2 h = __floats2half2_rn(lo, hi);
    return *(unsigned*)&h;
}

__device__ __forceinline__ float ex2f(float x) {
    float r;
    asm("ex2.approx.f32 %0, %1;" : "=f"(r) : "f"(x));
    return r;
}

__device__ __forceinline__ uint32_t smem_u32(const void* p) {
    uint32_t a;
    asm("{ .reg .u64 t; cvta.to.shared.u64 t, %1; cvt.u32.u64 %0, t; }"
        : "=r"(a) : "l"(p));
    return a;
}

#define CP_ASYNC16(dst, src) \
    asm volatile("cp.async.cg.shared.global [%0], [%1], 16;" \
                 :: "r"(dst), "l"(src) : "memory")
#define CP_COMMIT() asm volatile("cp.async.commit_group;" ::: "memory")
#define CP_WAIT(n)  asm volatile("cp.async.wait_group %0;" :: "n"(n) : "memory")

#define LDMATRIX_X4_TRANS(r0, r1, r2, r3, addr) \
    asm volatile("ldmatrix.sync.aligned.m8n8.x4.trans.shared.b16 {%0,%1,%2,%3}, [%4];" \
                 : "=r"(r0), "=r"(r1), "=r"(r2), "=r"(r3) : "r"(addr))

// ---------------------------------------------------------------------------
// Prep kernels
// ---------------------------------------------------------------------------
__global__ void to_fp16_kernel(const float* __restrict__ src,
                               __half* __restrict__ dst, int n8)
{
    int i = blockIdx.x * blockDim.x + threadIdx.x;
    if (i >= n8) return;
    float4 a = ((const float4*)src)[2 * i];
    float4 b = ((const float4*)src)[2 * i + 1];
    uint4 o;
    o.x = pack_h2(a.x, a.y);
    o.y = pack_h2(a.z, a.w);
    o.z = pack_h2(b.x, b.y);
    o.w = pack_h2(b.z, b.w);
    ((uint4*)dst)[i] = o;
}

// dst = fp16(src * log2e + BADD)
__global__ void bias_prep_kernel(const float* __restrict__ src,
                                 __half* __restrict__ dst, int n8)
{
    const float L = 1.4426950408889634f;
    int i = blockIdx.x * blockDim.x + threadIdx.x;
    if (i >= n8) return;
    float4 a = ((const float4*)src)[2 * i];
    float4 b = ((const float4*)src)[2 * i + 1];
    uint4 o;
    o.x = pack_h2(fmaf(a.x, L, BADD), fmaf(a.y, L, BADD));
    o.y = pack_h2(fmaf(a.z, L, BADD), fmaf(a.w, L, BADD));
    o.z = pack_h2(fmaf(b.x, L, BADD), fmaf(b.y, L, BADD));
    o.w = pack_h2(fmaf(b.z, L, BADD), fmaf(b.w, L, BADD));
    ((uint4*)dst)[i] = o;
}

// dst[C][R] = fp16(src[R][C]^T)
__global__ void transpose_fp16_kernel(const float* __restrict__ src,
                                      __half* __restrict__ dst, int R, int C)
{
    __shared__ float t[32][33];
    const int bx = blockIdx.x * 32;
    const int by = blockIdx.y * 32;
    const int x = threadIdx.x, y = threadIdx.y;
#pragma unroll
    for (int j = y; j < 32; j += 8)
        t[j][x] = src[(size_t)(by + j) * C + bx + x];
    __syncthreads();
#pragma unroll
    for (int j = y; j < 32; j += 8)
        dst[(size_t)(bx + j) * R + by + x] = __float2half_rn(t[x][j]);
}

// ---------------------------------------------------------------------------
// FP16 GEMM (round-12 form, best known): C = A[M,K] @ Bt[N,K]^T + bias.
// 128 threads, 4 warps of 64x64, BK=32 halves, 3-stage cp.async,
// per-ks scalar LDS fragment loads, trailing syncthreads intact.
// ---------------------------------------------------------------------------
#define GSTR 20
#define GTILE (128 * GSTR)
#define GEMM_SMEM (3 * 2 * GTILE * 4)      // 61440 bytes

template<bool SPLIT3>
__global__ __launch_bounds__(128, 2)
void gemm_fp16_kernel(const __half* __restrict__ A,
                      const __half* __restrict__ Bt,
                      const float* __restrict__ bias,
                      float* __restrict__ C0,
                      float* __restrict__ C1,
                      float* __restrict__ C2,
                      __half* __restrict__ H0,
                      __half* __restrict__ H1,
                      __half* __restrict__ H2,
                      int M, int N, int K)
{
    extern __shared__ unsigned smw[];
    const int tid  = threadIdx.x;
    const int warp = tid >> 5;
    const int lane = tid & 31;
    const int g    = lane >> 2;
    const int tg   = lane & 3;
    const int row0 = blockIdx.y * 128;
    const int col0 = blockIdx.x * 128;
    const int wm   = (warp >> 1) * 64;
    const int wn   = (warp & 1) * 64;

    const int lr  = tid >> 2;
    const int lcw = (tid & 3) * 4;
    const int lch = (tid & 3) * 8;

    auto issue = [&](int kt, int s) {
        const int k0 = kt * 32;
        unsigned* As = &smw[s * 2 * GTILE];
        unsigned* Bs = As + GTILE;
#pragma unroll
        for (int p = 0; p < 4; p++) {
            const int r = lr + p * 32;
            CP_ASYNC16(smem_u32(&As[r * GSTR + lcw]),
                       &A[(size_t)(row0 + r) * K + k0 + lch]);
            CP_ASYNC16(smem_u32(&Bs[r * GSTR + lcw]),
                       &Bt[(size_t)(col0 + r) * K + k0 + lch]);
        }
    };

    float acc[4][8][4];
#pragma unroll
    for (int mt = 0; mt < 4; mt++)
#pragma unroll
        for (int nt = 0; nt < 8; nt++)
#pragma unroll
            for (int i = 0; i < 4; i++) acc[mt][nt][i] = 0.0f;

    const int ksteps = K / 32;
    issue(0, 0); CP_COMMIT();
    issue(1, 1); CP_COMMIT();

    for (int kt = 0; kt < ksteps; kt++) {
        const int s = kt % 3;
        if (kt + 1 < ksteps) { CP_WAIT(1); } else { CP_WAIT(0); }
        __syncthreads();
        if (kt + 2 < ksteps) { issue(kt + 2, (kt + 2) % 3); CP_COMMIT(); }

        const unsigned* As = &smw[s * 2 * GTILE];
        const unsigned* Bs = As + GTILE;
#pragma unroll
        for (int ks = 0; ks < 2; ks++) {
            unsigned af[4][4];
#pragma unroll
            for (int mt = 0; mt < 4; mt++) {
                const int r = wm + mt * 16 + g;
                const int c = ks * 8 + tg;
                af[mt][0] = As[r * GSTR + c];
                af[mt][1] = As[(r + 8) * GSTR + c];
                af[mt][2] = As[r * GSTR + c + 4];
                af[mt][3] = As[(r + 8) * GSTR + c + 4];
            }
#pragma unroll
            for (int nt = 0; nt < 8; nt++) {
                unsigned bf[2];
                const int r = wn + nt * 8 + g;
                const int c = ks * 8 + tg;
                bf[0] = Bs[r * GSTR + c];
                bf[1] = Bs[r * GSTR + c + 4];
#pragma unroll
                for (int mt = 0; mt < 4; mt++)
                    mma_fp16(acc[mt][nt], af[mt], bf);
            }
        }
        __syncthreads();
    }

    // epilogue
    int seg = 0, ccol0 = col0, ldc = N;
    if (SPLIT3) {
        seg   = col0 >> 10;
        ccol0 = col0 - (seg << 10);
        ldc   = EE;
    }

#pragma unroll
    for (int mt = 0; mt < 4; mt++) {
        const int r0 = row0 + wm + mt * 16 + g;
#pragma unroll
        for (int nt = 0; nt < 8; nt++) {
            const int cg = col0 + wn + nt * 8 + 2 * tg;
            const int cs = ccol0 + wn + nt * 8 + 2 * tg;
            float2 bz = *(const float2*)&bias[cg];
            float v00 = acc[mt][nt][0] + bz.x, v01 = acc[mt][nt][1] + bz.y;
            float v10 = acc[mt][nt][2] + bz.x, v11 = acc[mt][nt][3] + bz.y;
            if (SPLIT3) {
                if (seg == 0) {
                    *(unsigned*)&H0[(size_t)r0 * EE + cs] =
                        pack_h2(v00 * QSCALE, v01 * QSCALE);
                    *(unsigned*)&H0[(size_t)(r0 + 8) * EE + cs] =
                        pack_h2(v10 * QSCALE, v11 * QSCALE);
                } else {
                    float* Cf = (seg == 1) ? C1 : C2;
                    __half* Hf = (seg == 1) ? H1 : H2;
                    *(float2*)&Cf[(size_t)r0 * EE + cs]       = make_float2(v00, v01);
                    *(float2*)&Cf[(size_t)(r0 + 8) * EE + cs] = make_float2(v10, v11);
                    *(unsigned*)&Hf[(size_t)r0 * EE + cs]       = pack_h2(v00, v01);
                    *(unsigned*)&Hf[(size_t)(r0 + 8) * EE + cs] = pack_h2(v10, v11);
                }
            } else {
                *(float2*)&C0[(size_t)r0 * ldc + cs]       = make_float2(v00, v01);
                *(float2*)&C0[(size_t)(r0 + 8) * ldc + cs] = make_float2(v10, v11);
            }
        }
    }
}

// ---------------------------------------------------------------------------
// FP16 flash attention v5: 256 threads (8 warps x 16 q-rows), q-tile 128,
// P-in-register, base-2 softmax with folded fp16 bias, k-tile 64,
// cp.async double buffer. 2 CTAs/SM -> 16 warps/SM for latency hiding.
// smem words: K[2][64*36] | V[2][64*36] | Q[128*36]
// ---------------------------------------------------------------------------
#define ASTR 36
#define KBUF (64 * ASTR)
#define VBUF (64 * ASTR)
#define SMA_K 0
#define SMA_V (2 * KBUF)
#define SMA_Q (SMA_V + 2 * VBUF)
#define ATTN_SMEM ((SMA_Q + 128 * ASTR) * 4)   // 55296 bytes

__global__ __launch_bounds__(256, 2)
void flash_attn_fp16_kernel(const __half* __restrict__ qsrc,
                            const __half* __restrict__ ksrc,
                            const __half* __restrict__ vsrc,
                            const __half* __restrict__ b2h,
                            __half* __restrict__ ctx)
{
    extern __shared__ unsigned smw[];

    const int qb   = gridDim.x - 1 - blockIdx.x;   // largest tiles first
    const int h    = blockIdx.y;
    const int b    = blockIdx.z;
    const int tid  = threadIdx.x;
    const int warp = tid >> 5;
    const int lane = tid & 31;
    const int g    = lane >> 2;
    const int tg   = lane & 3;
    const int w16  = warp * 16;

    const int tok0 = b * SS;

    auto issue_kv = [&](int kb, int buf) {
#pragma unroll
        for (int p = 0; p < 2; p++) {
            const int idx = tid + p * 256;          // 0..511 16B chunks
            const int r = idx >> 3, ch = idx & 7;
            const size_t gi = (size_t)(tok0 + kb * 64 + r) * EE + h * DH + ch * 8;
            CP_ASYNC16(smem_u32(&smw[SMA_K + buf * KBUF + r * ASTR + ch * 4]), &ksrc[gi]);
            CP_ASYNC16(smem_u32(&smw[SMA_V + buf * VBUF + r * ASTR + ch * 4]), &vsrc[gi]);
        }
    };

    // prologue: Q tile (128x64 halves = 1024 chunks) + KV tile 0 in group 0
#pragma unroll
    for (int p = 0; p < 4; p++) {
        const int idx = tid + p * 256;
        const int r = idx >> 3, ch = idx & 7;
        CP_ASYNC16(smem_u32(&smw[SMA_Q + r * ASTR + ch * 4]),
                   &qsrc[(size_t)(tok0 + qb * 128 + r) * EE + h * DH + ch * 8]);
    }
    issue_kv(0, 0);
    CP_COMMIT();

    unsigned qa[4][4];                  // [ks][frag]
    float out[8][4];
    float rs0 = 0.0f, rs1 = 0.0f;
#pragma unroll
    for (int nt = 0; nt < 8; nt++)
#pragma unroll
        for (int i = 0; i < 4; i++) out[nt][i] = 0.0f;

    const int qg0 = qb * 128 + w16 + g;
    const int qg1 = qg0 + 8;
    const int nkb = 2 * qb + 2;

    for (int kb = 0; kb < nkb; kb++) {
        const int buf = kb & 1;
        if (kb + 1 < nkb) { issue_kv(kb + 1, (kb + 1) & 1); CP_COMMIT(); CP_WAIT(1); }
        else              { CP_WAIT(0); }
        __syncthreads();

        if (kb == 0) {
            // Q fragments to registers (own 16-row band, scalar LDS)
#pragma unroll
            for (int ks = 0; ks < 4; ks++) {
                const int r = w16 + g;
                qa[ks][0] = smw[SMA_Q + r * ASTR + ks * 8 + tg];
                qa[ks][1] = smw[SMA_Q + (r + 8) * ASTR + ks * 8 + tg];
                qa[ks][2] = smw[SMA_Q + r * ASTR + ks * 8 + tg + 4];
                qa[ks][3] = smw[SMA_Q + (r + 8) * ASTR + ks * 8 + tg + 4];
            }
        }

        const unsigned* Ks = &smw[SMA_K + buf * KBUF];
        const uint32_t  Vbase = smem_u32(&smw[SMA_V + buf * VBUF]);

        // S = Q K^T  (16x64 per warp), log2 domain
        float s[8][4];
#pragma unroll
        for (int nt = 0; nt < 8; nt++)
#pragma unroll
            for (int i = 0; i < 4; i++) s[nt][i] = 0.0f;
#pragma unroll
        for (int ks = 0; ks < 4; ks++) {
#pragma unroll
            for (int nt = 0; nt < 8; nt++) {
                unsigned bf[2];
                bf[0] = Ks[(nt * 8 + g) * ASTR + ks * 8 + tg];
                bf[1] = Ks[(nt * 8 + g) * ASTR + ks * 8 + tg + 4];
                mma_fp16(s[nt], qa[ks], bf);
            }
        }

        // fused softmax epilogue + PV per 16-key step (P in registers)
        const bool need_mask = (kb * 64 + 63) > qg0;
#pragma unroll
        for (int ks = 0; ks < 4; ks++) {
            unsigned pa[4];
#pragma unroll
            for (int j = 0; j < 2; j++) {
                const int nt = 2 * ks + j;
                const int kg = kb * 64 + nt * 8 + 2 * tg;
                float2 bz0 = __half22float2(*(const __half2*)&b2h[(size_t)qg0 * SS + kg]);
                float2 bz1 = __half22float2(*(const __half2*)&b2h[(size_t)qg1 * SS + kg]);
                float p0 = ex2f(s[nt][0] + bz0.x);
                float p1 = ex2f(s[nt][1] + bz0.y);
                float p2 = ex2f(s[nt][2] + bz1.x);
                float p3 = ex2f(s[nt][3] + bz1.y);
                if (need_mask) {
                    if (kg     > qg0) p0 = 0.0f;
                    if (kg + 1 > qg0) p1 = 0.0f;
                    if (kg     > qg1) p2 = 0.0f;
                    if (kg + 1 > qg1) p3 = 0.0f;
                }
                rs0 += p0 + p1;
                rs1 += p2 + p3;
                pa[2 * j]     = pack_h2(p0, p1);
                pa[2 * j + 1] = pack_h2(p2, p3);
            }
#pragma unroll
            for (int np = 0; np < 4; np++) {
                const int krow = ks * 16 + (lane & 7) + ((lane >> 3) & 1) * 8;
                const int dcol = np * 16 + (lane >> 4) * 8;
                uint32_t addr = Vbase + (krow * ASTR) * 4 + dcol * 2;
                unsigned r0, r1, r2, r3;
                LDMATRIX_X4_TRANS(r0, r1, r2, r3, addr);
                unsigned bf0[2] = {r0, r1};
                unsigned bf1[2] = {r2, r3};
                mma_fp16(out[2 * np],     pa, bf0);
                mma_fp16(out[2 * np + 1], pa, bf1);
            }
        }
        __syncthreads();   // protect K/V buffers before re-issue (2 buffers)
    }

    // final row-sum reduction across the tg quad
    rs0 += __shfl_xor_sync(0xffffffffu, rs0, 1);
    rs0 += __shfl_xor_sync(0xffffffffu, rs0, 2);
    rs1 += __shfl_xor_sync(0xffffffffu, rs1, 1);
    rs1 += __shfl_xor_sync(0xffffffffu, rs1, 2);

    // write ctx fp16 (feeds proj GEMM)
    const float il0 = 1.0f / rs0, il1 = 1.0f / rs1;
    const int trow = tok0 + qb * 128 + w16 + g;
#pragma unroll
    for (int nt = 0; nt < 8; nt++) {
        const int c = h * DH + nt * 8 + 2 * tg;
        *(unsigned*)&ctx[(size_t)trow * EE + c] =
            pack_h2(out[nt][0] * il0, out[nt][1] * il0);
        *(unsigned*)&ctx[(size_t)(trow + 8) * EE + c] =
            pack_h2(out[nt][2] * il1, out[nt][3] * il1);
    }
}

// ---------------------------------------------------------------------------
// kernel_launch
// ---------------------------------------------------------------------------
extern "C" void kernel_launch(void* const* d_in, const int* in_sizes, int n_in,
                              void* d_out, int out_size)
{
    const float* hidden = (const float*)d_in[0];
    const float* bias   = (const float*)d_in[1];
    const float* Wqkv   = (const float*)d_in[2];
    const float* bqkv   = (const float*)d_in[3];
    const float* Wproj  = (const float*)d_in[4];
    const float* bproj  = (const float*)d_in[5];
    float* out = (float*)d_out;

    __half *ah, *wqkvh, *wprojh, *qh, *kh, *vh, *ctxh, *b2h;
    cudaGetSymbolAddress((void**)&ah, g_ah);
    cudaGetSymbolAddress((void**)&wqkvh, g_wqkvh);
    cudaGetSymbolAddress((void**)&wprojh, g_wprojh);
    cudaGetSymbolAddress((void**)&qh, g_qh);
    cudaGetSymbolAddress((void**)&kh, g_kh);
    cudaGetSymbolAddress((void**)&vh, g_vh);
    cudaGetSymbolAddress((void**)&ctxh, g_ctxh);
    cudaGetSymbolAddress((void**)&b2h, g_b2h);

    float* out_attn = out;
    float* out_key  = out + (size_t)M_TOK * EE;
    float* out_val  = out + (size_t)2 * M_TOK * EE;

    cudaFuncSetAttribute(flash_attn_fp16_kernel,
                         cudaFuncAttributeMaxDynamicSharedMemorySize, ATTN_SMEM);
    cudaFuncSetAttribute(gemm_fp16_kernel<true>,
                         cudaFuncAttributeMaxDynamicSharedMemorySize, GEMM_SMEM);
    cudaFuncSetAttribute(gemm_fp16_kernel<false>,
                         cudaFuncAttributeMaxDynamicSharedMemorySize, GEMM_SMEM);

    // 0) prep: fp16 conversions (hidden, weights^T, folded bias)
    to_fp16_kernel<<<(M_TOK * EE / 8 + 255) / 256, 256>>>(hidden, ah, M_TOK * EE / 8);
    bias_prep_kernel<<<(SS * SS / 8 + 255) / 256, 256>>>(bias, b2h, SS * SS / 8);
    {
        dim3 blk(32, 8);
        transpose_fp16_kernel<<<dim3(N_QKV / 32, EE / 32), blk>>>(Wqkv, wqkvh, EE, N_QKV);
        transpose_fp16_kernel<<<dim3(EE / 32, EE / 32), blk>>>(Wproj, wprojh, EE, EE);
    }

    // 1) QKV GEMM: q -> fp16 scratch (scaled); k/v -> fp32 cache + fp16 scratch
    {
        dim3 grid(N_QKV / 128, M_TOK / 128);
        gemm_fp16_kernel<true><<<grid, 128, GEMM_SMEM>>>(
            ah, wqkvh, bqkv,
            nullptr, out_key, out_val,
            qh, kh, vh,
            M_TOK, N_QKV, EE);
    }
    // 2) attention
    {
        dim3 grid(SS / 128, HH, BB);
        flash_attn_fp16_kernel<<<grid, 256, ATTN_SMEM>>>(qh, kh, vh, b2h, ctxh);
    }
    // 3) projection (fp32 output)
    {
        dim3 grid(EE / 128, M_TOK / 128);
        gemm_fp16_kernel<false><<<grid, 128, GEMM_SMEM>>>(
            ctxh, wprojh, bproj,
            out_attn, nullptr, nullptr,
            nullptr, nullptr, nullptr,
            M_TOK, EE, EE);
    }
}

// round 16
// speedup vs baseline: 1.0078x; 1.0078x over previous
#include <cuda_runtime.h>
#include <cuda_fp16.h>
#include <stdint.h>
#include <math.h>

// Problem constants
#define BB 2
#define SS 2048
#define EE 1024
#define HH 16
#define DH 64
#define M_TOK (BB * SS)        // 4096
#define N_QKV (3 * EE)         // 3072

// Scratch (__device__ globals; no allocations allowed)
__device__ __half g_ah[M_TOK * EE];       // hidden, fp16
__device__ __half g_wqkvh[N_QKV * EE];    // Wqkv^T fp16 [3072,1024]
__device__ __half g_wprojh[EE * EE];      // Wproj^T fp16
__device__ __half g_qh[M_TOK * EE];       // Q fp16, pre-scaled by 0.125
__device__ __half g_kh[M_TOK * EE];       // K fp16
__device__ __half g_vh[M_TOK * EE];       // V fp16
__device__ __half g_ctxh[M_TOK * EE];     // attention output fp16

// ---------------------------------------------------------------------------
// helpers
// ---------------------------------------------------------------------------
__device__ __forceinline__ void mma_fp16(float c[4], const unsigned a[4], const unsigned b[2]) {
    asm volatile(
        "mma.sync.aligned.m16n8k16.row.col.f32.f16.f16.f32 "
        "{%0,%1,%2,%3}, {%4,%5,%6,%7}, {%8,%9}, {%0,%1,%2,%3};"
        : "+f"(c[0]), "+f"(c[1]), "+f"(c[2]), "+f"(c[3])
        : "r"(a[0]), "r"(a[1]), "r"(a[2]), "r"(a[3]), "r"(b[0]), "r"(b[1]));
}

__device__ __forceinline__ unsigned pack_h2(float lo, float hi) {
    __half2 h = __floats2half2_rn(lo, hi);
    return *(unsigned*)&h;
}

__device__ __forceinline__ uint32_t smem_u32(const void* p) {
    uint32_t a;
    asm("{ .reg .u64 t; cvta.to.shared.u64 t, %1; cvt.u32.u64 %0, t; }"
        : "=r"(a) : "l"(p));
    return a;
}

#define CP_ASYNC16(dst, src) \
    asm volatile("cp.async.cg.shared.global [%0], [%1], 16;" \
                 :: "r"(dst), "l"(src) : "memory")
#define CP_COMMIT() asm volatile("cp.async.commit_group;" ::: "memory")
#define CP_WAIT(n)  asm volatile("cp.async.wait_group %0;" :: "n"(n) : "memory")

#define LDMATRIX_X4_TRANS(r0, r1, r2, r3, addr) \
    asm volatile("ldmatrix.sync.aligned.m8n8.x4.trans.shared.b16 {%0,%1,%2,%3}, [%4];" \
                 : "=r"(r0), "=r"(r1), "=r"(r2), "=r"(r3) : "r"(addr))

// ---------------------------------------------------------------------------
// Prep kernels: fp32 -> fp16 (round-to-nearest)
// ---------------------------------------------------------------------------
__global__ void to_fp16_kernel(const float* __restrict__ src,
                               __half* __restrict__ dst, int n8)
{
    int i = blockIdx.x * blockDim.x + threadIdx.x;
    if (i >= n8) return;
    float4 a = ((const float4*)src)[2 * i];
    float4 b = ((const float4*)src)[2 * i + 1];
    uint4 o;
    o.x = pack_h2(a.x, a.y);
    o.y = pack_h2(a.z, a.w);
    o.z = pack_h2(b.x, b.y);
    o.w = pack_h2(b.z, b.w);
    ((uint4*)dst)[i] = o;
}

// dst[C][R] = fp16(src[R][C]^T)
__global__ void transpose_fp16_kernel(const float* __restrict__ src,
                                      __half* __restrict__ dst, int R, int C)
{
    __shared__ float t[32][33];
    const int bx = blockIdx.x * 32;
    const int by = blockIdx.y * 32;
    const int x = threadIdx.x, y = threadIdx.y;
#pragma unroll
    for (int j = y; j < 32; j += 8)
        t[j][x] = src[(size_t)(by + j) * C + bx + x];
    __syncthreads();
#pragma unroll
    for (int j = y; j < 32; j += 8)
        dst[(size_t)(bx + j) * R + by + x] = __float2half_rn(t[x][j]);
}

// ---------------------------------------------------------------------------
// FP16 GEMM (round-11 form, trailing syncthreads removed):
// C = A[M,K] @ Bt[N,K]^T + bias.
// 128 threads, 4 warps of 64x64, BK=32 halves, 3-stage cp.async,
// per-ks scalar LDS fragment loads.
// Safety of single barrier per tile: every fragment LDS is consumed by an
// HMMA before the barrier (scoreboard forces LDS completion before HMMA
// issue, which precedes BAR in program order), so the leading CP_WAIT+sync
// of iteration kt fully orders reuse of stage (kt+2)%3.
// ---------------------------------------------------------------------------
#define GSTR 20
#define GTILE (128 * GSTR)
#define GEMM_SMEM (3 * 2 * GTILE * 4)      // 61440 bytes

template<bool SPLIT3>
__global__ __launch_bounds__(128, 2)
void gemm_fp16_kernel(const __half* __restrict__ A,
                      const __half* __restrict__ Bt,
                      const float* __restrict__ bias,
                      float* __restrict__ C0,
                      float* __restrict__ C1,
                      float* __restrict__ C2,
                      __half* __restrict__ H0,
                      __half* __restrict__ H1,
                      __half* __restrict__ H2,
                      int M, int N, int K)
{
    extern __shared__ unsigned smw[];
    const int tid  = threadIdx.x;
    const int warp = tid >> 5;
    const int lane = tid & 31;
    const int g    = lane >> 2;
    const int tg   = lane & 3;
    const int row0 = blockIdx.y * 128;
    const int col0 = blockIdx.x * 128;
    const int wm   = (warp >> 1) * 64;
    const int wn   = (warp & 1) * 64;

    const int lr  = tid >> 2;
    const int lcw = (tid & 3) * 4;
    const int lch = (tid & 3) * 8;

    auto issue = [&](int kt, int s) {
        const int k0 = kt * 32;
        unsigned* As = &smw[s * 2 * GTILE];
        unsigned* Bs = As + GTILE;
#pragma unroll
        for (int p = 0; p < 4; p++) {
            const int r = lr + p * 32;
            CP_ASYNC16(smem_u32(&As[r * GSTR + lcw]),
                       &A[(size_t)(row0 + r) * K + k0 + lch]);
            CP_ASYNC16(smem_u32(&Bs[r * GSTR + lcw]),
                       &Bt[(size_t)(col0 + r) * K + k0 + lch]);
        }
    };

    float acc[4][8][4];
#pragma unroll
    for (int mt = 0; mt < 4; mt++)
#pragma unroll
        for (int nt = 0; nt < 8; nt++)
#pragma unroll
            for (int i = 0; i < 4; i++) acc[mt][nt][i] = 0.0f;

    const int ksteps = K / 32;
    issue(0, 0); CP_COMMIT();
    issue(1, 1); CP_COMMIT();

    for (int kt = 0; kt < ksteps; kt++) {
        const int s = kt % 3;
        if (kt + 1 < ksteps) { CP_WAIT(1); } else { CP_WAIT(0); }
        __syncthreads();
        if (kt + 2 < ksteps) { issue(kt + 2, (kt + 2) % 3); CP_COMMIT(); }

        const unsigned* As = &smw[s * 2 * GTILE];
        const unsigned* Bs = As + GTILE;
#pragma unroll
        for (int ks = 0; ks < 2; ks++) {
            unsigned af[4][4];
#pragma unroll
            for (int mt = 0; mt < 4; mt++) {
                const int r = wm + mt * 16 + g;
                const int c = ks * 8 + tg;
                af[mt][0] = As[r * GSTR + c];
                af[mt][1] = As[(r + 8) * GSTR + c];
                af[mt][2] = As[r * GSTR + c + 4];
                af[mt][3] = As[(r + 8) * GSTR + c + 4];
            }
#pragma unroll
            for (int nt = 0; nt < 8; nt++) {
                unsigned bf[2];
                const int r = wn + nt * 8 + g;
                const int c = ks * 8 + tg;
                bf[0] = Bs[r * GSTR + c];
                bf[1] = Bs[r * GSTR + c + 4];
#pragma unroll
                for (int mt = 0; mt < 4; mt++)
                    mma_fp16(acc[mt][nt], af[mt], bf);
            }
        }
        // (no trailing syncthreads — see header comment)
    }

    // epilogue
    int seg = 0, ccol0 = col0, ldc = N;
    if (SPLIT3) {
        seg   = col0 >> 10;
        ccol0 = col0 - (seg << 10);
        ldc   = EE;
    }

#pragma unroll
    for (int mt = 0; mt < 4; mt++) {
        const int r0 = row0 + wm + mt * 16 + g;
#pragma unroll
        for (int nt = 0; nt < 8; nt++) {
            const int cg = col0 + wn + nt * 8 + 2 * tg;
            const int cs = ccol0 + wn + nt * 8 + 2 * tg;
            float2 bz = *(const float2*)&bias[cg];
            float v00 = acc[mt][nt][0] + bz.x, v01 = acc[mt][nt][1] + bz.y;
            float v10 = acc[mt][nt][2] + bz.x, v11 = acc[mt][nt][3] + bz.y;
            if (SPLIT3) {
                if (seg == 0) {
                    *(unsigned*)&H0[(size_t)r0 * EE + cs] =
                        pack_h2(v00 * 0.125f, v01 * 0.125f);
                    *(unsigned*)&H0[(size_t)(r0 + 8) * EE + cs] =
                        pack_h2(v10 * 0.125f, v11 * 0.125f);
                } else {
                    float* Cf = (seg == 1) ? C1 : C2;
                    __half* Hf = (seg == 1) ? H1 : H2;
                    *(float2*)&Cf[(size_t)r0 * EE + cs]       = make_float2(v00, v01);
                    *(float2*)&Cf[(size_t)(r0 + 8) * EE + cs] = make_float2(v10, v11);
                    *(unsigned*)&Hf[(size_t)r0 * EE + cs]       = pack_h2(v00, v01);
                    *(unsigned*)&Hf[(size_t)(r0 + 8) * EE + cs] = pack_h2(v10, v11);
                }
            } else {
                *(float2*)&C0[(size_t)r0 * ldc + cs]       = make_float2(v00, v01);
                *(float2*)&C0[(size_t)(r0 + 8) * ldc + cs] = make_float2(v10, v11);
            }
        }
    }
}

// ---------------------------------------------------------------------------
// FP16 flash attention (round-11 form, the measured best): P-in-register,
// fixed-shift softmax (C=4, P scaled x32, fp32 bias), 128 threads
// (4 warps x 32 q-rows), q-tile 128, k-tile 64, cp.async double buffer.
// smem words: K[2][64*36] | V[2][64*36] | Q[128*36]
// ---------------------------------------------------------------------------
#define ASTR 36
#define KBUF (64 * ASTR)
#define VBUF (64 * ASTR)
#define SMA_K 0
#define SMA_V (2 * KBUF)
#define SMA_Q (SMA_V + 2 * VBUF)
#define ATTN_SMEM ((SMA_Q + 128 * ASTR) * 4)   // 55296 bytes
#define SOFTMAX_C 4.0f
#define PSCALE 32.0f

__global__ __launch_bounds__(128, 2)
void flash_attn_fp16_kernel(const __half* __restrict__ qsrc,
                            const __half* __restrict__ ksrc,
                            const __half* __restrict__ vsrc,
                            const float* __restrict__ bias,
                            __half* __restrict__ ctx)
{
    extern __shared__ unsigned smw[];

    const int qb   = gridDim.x - 1 - blockIdx.x;   // largest tiles first
    const int h    = blockIdx.y;
    const int b    = blockIdx.z;
    const int tid  = threadIdx.x;
    const int warp = tid >> 5;
    const int lane = tid & 31;
    const int g    = lane >> 2;
    const int tg   = lane & 3;
    const int w32  = warp * 32;

    const int tok0 = b * SS;

    auto issue_kv = [&](int kb, int buf) {
#pragma unroll
        for (int p = 0; p < 4; p++) {
            const int idx = tid + p * 128;
            const int r = idx >> 3, ch = idx & 7;
            const size_t gi = (size_t)(tok0 + kb * 64 + r) * EE + h * DH + ch * 8;
            CP_ASYNC16(smem_u32(&smw[SMA_K + buf * KBUF + r * ASTR + ch * 4]), &ksrc[gi]);
            CP_ASYNC16(smem_u32(&smw[SMA_V + buf * VBUF + r * ASTR + ch * 4]), &vsrc[gi]);
        }
    };

    // prologue: Q tile + KV tile 0 in group 0
#pragma unroll
    for (int p = 0; p < 8; p++) {
        const int idx = tid + p * 128;
        const int r = idx >> 3, ch = idx & 7;
        CP_ASYNC16(smem_u32(&smw[SMA_Q + r * ASTR + ch * 4]),
                   &qsrc[(size_t)(tok0 + qb * 128 + r) * EE + h * DH + ch * 8]);
    }
    issue_kv(0, 0);
    CP_COMMIT();

    unsigned qa[4][2][4];               // [ks][mt][frag]
    float out[2][8][4];
    float rs[2][2];
#pragma unroll
    for (int mt = 0; mt < 2; mt++) {
        rs[mt][0] = 0.0f; rs[mt][1] = 0.0f;
#pragma unroll
        for (int nt = 0; nt < 8; nt++)
#pragma unroll
            for (int i = 0; i < 4; i++) out[mt][nt][i] = 0.0f;
    }

    int qg[2][2];
#pragma unroll
    for (int mt = 0; mt < 2; mt++) {
        qg[mt][0] = qb * 128 + w32 + mt * 16 + g;
        qg[mt][1] = qg[mt][0] + 8;
    }
    const int nkb = 2 * qb + 2;

    for (int kb = 0; kb < nkb; kb++) {
        const int buf = kb & 1;
        if (kb + 1 < nkb) { issue_kv(kb + 1, (kb + 1) & 1); CP_COMMIT(); CP_WAIT(1); }
        else              { CP_WAIT(0); }
        __syncthreads();

        if (kb == 0) {
            // Q fragments to registers (scalar LDS)
#pragma unroll
            for (int ks = 0; ks < 4; ks++)
#pragma unroll
                for (int mt = 0; mt < 2; mt++) {
                    const int r = w32 + mt * 16 + g;
                    qa[ks][mt][0] = smw[SMA_Q + r * ASTR + ks * 8 + tg];
                    qa[ks][mt][1] = smw[SMA_Q + (r + 8) * ASTR + ks * 8 + tg];
                    qa[ks][mt][2] = smw[SMA_Q + r * ASTR + ks * 8 + tg + 4];
                    qa[ks][mt][3] = smw[SMA_Q + (r + 8) * ASTR + ks * 8 + tg + 4];
                }
        }

        const unsigned* Ks = &smw[SMA_K + buf * KBUF];
        const uint32_t  Vbase = smem_u32(&smw[SMA_V + buf * VBUF]);

        // S = Q K^T  (32x64 per warp)
        float s[2][8][4];
#pragma unroll
        for (int mt = 0; mt < 2; mt++)
#pragma unroll
            for (int nt = 0; nt < 8; nt++)
#pragma unroll
                for (int i = 0; i < 4; i++) s[mt][nt][i] = 0.0f;
#pragma unroll
        for (int ks = 0; ks < 4; ks++) {
#pragma unroll
            for (int nt = 0; nt < 8; nt++) {
                unsigned bf[2];
                bf[0] = Ks[(nt * 8 + g) * ASTR + ks * 8 + tg];
                bf[1] = Ks[(nt * 8 + g) * ASTR + ks * 8 + tg + 4];
                mma_fp16(s[0][nt], qa[ks][0], bf);
                mma_fp16(s[1][nt], qa[ks][1], bf);
            }
        }

        // fused softmax epilogue + PV, one k-step (16 keys) at a time.
        const bool need_mask = (kb * 64 + 63) > qg[0][0];
#pragma unroll
        for (int ks = 0; ks < 4; ks++) {
            unsigned pa[2][4];
#pragma unroll
            for (int mt = 0; mt < 2; mt++) {
#pragma unroll
                for (int j = 0; j < 2; j++) {
                    const int nt = 2 * ks + j;
                    const int kg = kb * 64 + nt * 8 + 2 * tg;
                    float2 bz0 = *(const float2*)&bias[(size_t)qg[mt][0] * SS + kg];
                    float2 bz1 = *(const float2*)&bias[(size_t)qg[mt][1] * SS + kg];
                    float v0 = s[mt][nt][0] + bz0.x - SOFTMAX_C;
                    float v1 = s[mt][nt][1] + bz0.y - SOFTMAX_C;
                    float v2 = s[mt][nt][2] + bz1.x - SOFTMAX_C;
                    float v3 = s[mt][nt][3] + bz1.y - SOFTMAX_C;
                    if (need_mask) {
                        if (kg     > qg[mt][0]) v0 = -1e9f;
                        if (kg + 1 > qg[mt][0]) v1 = -1e9f;
                        if (kg     > qg[mt][1]) v2 = -1e9f;
                        if (kg + 1 > qg[mt][1]) v3 = -1e9f;
                    }
                    float p0 = __expf(v0) * PSCALE, p1 = __expf(v1) * PSCALE;
                    float p2 = __expf(v2) * PSCALE, p3 = __expf(v3) * PSCALE;
                    rs[mt][0] += p0 + p1;
                    rs[mt][1] += p2 + p3;
                    pa[mt][2 * j]     = pack_h2(p0, p1);
                    pa[mt][2 * j + 1] = pack_h2(p2, p3);
                }
            }
            // out += P V for this 16-key step (V via ldmatrix.trans)
#pragma unroll
            for (int np = 0; np < 4; np++) {
                const int krow = ks * 16 + (lane & 7) + ((lane >> 3) & 1) * 8;
                const int dcol = np * 16 + (lane >> 4) * 8;
                uint32_t addr = Vbase + (krow * ASTR) * 4 + dcol * 2;
                unsigned r0, r1, r2, r3;
                LDMATRIX_X4_TRANS(r0, r1, r2, r3, addr);
                unsigned bf0[2] = {r0, r1};
                unsigned bf1[2] = {r2, r3};
                mma_fp16(out[0][2 * np],     pa[0], bf0);
                mma_fp16(out[1][2 * np],     pa[1], bf0);
                mma_fp16(out[0][2 * np + 1], pa[0], bf1);
                mma_fp16(out[1][2 * np + 1], pa[1], bf1);
            }
        }
        __syncthreads();   // protect K/V buffers before re-issue
    }

    // final row-sum reduction across the tg quad
#pragma unroll
    for (int mt = 0; mt < 2; mt++)
#pragma unroll
        for (int j = 0; j < 2; j++) {
            rs[mt][j] += __shfl_xor_sync(0xffffffffu, rs[mt][j], 1);
            rs[mt][j] += __shfl_xor_sync(0xffffffffu, rs[mt][j], 2);
        }

    // write ctx fp16 (feeds proj GEMM)
#pragma unroll
    for (int mt = 0; mt < 2; mt++) {
        const float il0 = 1.0f / rs[mt][0], il1 = 1.0f / rs[mt][1];
        const int trow = tok0 + qb * 128 + w32 + mt * 16 + g;
#pragma unroll
        for (int nt = 0; nt < 8; nt++) {
            const int c = h * DH + nt * 8 + 2 * tg;
            *(unsigned*)&ctx[(size_t)trow * EE + c] =
                pack_h2(out[mt][nt][0] * il0, out[mt][nt][1] * il0);
            *(unsigned*)&ctx[(size_t)(trow + 8) * EE + c] =
                pack_h2(out[mt][nt][2] * il1, out[mt][nt][3] * il1);
        }
    }
}

// ---------------------------------------------------------------------------
// kernel_launch
// ---------------------------------------------------------------------------
extern "C" void kernel_launch(void* const* d_in, const int* in_sizes, int n_in,
                              void* d_out, int out_size)
{
    const float* hidden = (const float*)d_in[0];
    const float* bias   = (const float*)d_in[1];
    const float* Wqkv   = (const float*)d_in[2];
    const float* bqkv   = (const float*)d_in[3];
    const float* Wproj  = (const float*)d_in[4];
    const float* bproj  = (const float*)d_in[5];
    float* out = (float*)d_out;

    __half *ah, *wqkvh, *wprojh, *qh, *kh, *vh, *ctxh;
    cudaGetSymbolAddress((void**)&ah, g_ah);
    cudaGetSymbolAddress((void**)&wqkvh, g_wqkvh);
    cudaGetSymbolAddress((void**)&wprojh, g_wprojh);
    cudaGetSymbolAddress((void**)&qh, g_qh);
    cudaGetSymbolAddress((void**)&kh, g_kh);
    cudaGetSymbolAddress((void**)&vh, g_vh);
    cudaGetSymbolAddress((void**)&ctxh, g_ctxh);

    float* out_attn = out;
    float* out_key  = out + (size_t)M_TOK * EE;
    float* out_val  = out + (size_t)2 * M_TOK * EE;

    cudaFuncSetAttribute(flash_attn_fp16_kernel,
                         cudaFuncAttributeMaxDynamicSharedMemorySize, ATTN_SMEM);
    cudaFuncSetAttribute(gemm_fp16_kernel<true>,
                         cudaFuncAttributeMaxDynamicSharedMemorySize, GEMM_SMEM);
    cudaFuncSetAttribute(gemm_fp16_kernel<false>,
                         cudaFuncAttributeMaxDynamicSharedMemorySize, GEMM_SMEM);

    // 0) prep: convert hidden + transposed weights to fp16
    to_fp16_kernel<<<(M_TOK * EE / 8 + 255) / 256, 256>>>(hidden, ah, M_TOK * EE / 8);
    {
        dim3 blk(32, 8);
        transpose_fp16_kernel<<<dim3(N_QKV / 32, EE / 32), blk>>>(Wqkv, wqkvh, EE, N_QKV);
        transpose_fp16_kernel<<<dim3(EE / 32, EE / 32), blk>>>(Wproj, wprojh, EE, EE);
    }

    // 1) QKV GEMM: q -> fp16 scratch (scaled); k/v -> fp32 cache + fp16 scratch
    {
        dim3 grid(N_QKV / 128, M_TOK / 128);
        gemm_fp16_kernel<true><<<grid, 128, GEMM_SMEM>>>(
            ah, wqkvh, bqkv,
            nullptr, out_key, out_val,
            qh, kh, vh,
            M_TOK, N_QKV, EE);
    }
    // 2) attention
    {
        dim3 grid(SS / 128, HH, BB);
        flash_attn_fp16_kernel<<<grid, 128, ATTN_SMEM>>>(qh, kh, vh, bias, ctxh);
    }
    // 3) projection (fp32 output)
    {
        dim3 grid(EE / 128, M_TOK / 128);
        gemm_fp16_kernel<false><<<grid, 128, GEMM_SMEM>>>(
            ctxh, wprojh, bproj,
            out_attn, nullptr, nullptr,
            nullptr, nullptr, nullptr,
            M_TOK, EE, EE);
    }
}

// round 17
// speedup vs baseline: 1.0448x; 1.0367x over previous
#include <cuda_runtime.h>
#include <cuda_fp16.h>
#include <stdint.h>
#include <math.h>

// Problem constants
#define BB 2
#define SS 2048
#define EE 1024
#define HH 16
#define DH 64
#define M_TOK (BB * SS)        // 4096
#define N_QKV (3 * EE)         // 3072

// Scratch (__device__ globals; no allocations allowed)
__device__ __half g_ah[M_TOK * EE];       // hidden, fp16
__device__ __half g_wqkvh[N_QKV * EE];    // Wqkv^T fp16 [3072,1024]
__device__ __half g_wprojh[EE * EE];      // Wproj^T fp16
__device__ __half g_qh[M_TOK * EE];       // Q fp16, pre-scaled by 0.125
__device__ __half g_kh[M_TOK * EE];       // K fp16
__device__ __half g_vh[M_TOK * EE];       // V fp16
__device__ __half g_ctxh[M_TOK * EE];     // attention output fp16

// ---------------------------------------------------------------------------
// helpers
// ---------------------------------------------------------------------------
__device__ __forceinline__ void mma_fp16(float c[4], const unsigned a[4], const unsigned b[2]) {
    asm volatile(
        "mma.sync.aligned.m16n8k16.row.col.f32.f16.f16.f32 "
        "{%0,%1,%2,%3}, {%4,%5,%6,%7}, {%8,%9}, {%0,%1,%2,%3};"
        : "+f"(c[0]), "+f"(c[1]), "+f"(c[2]), "+f"(c[3])
        : "r"(a[0]), "r"(a[1]), "r"(a[2]), "r"(a[3]), "r"(b[0]), "r"(b[1]));
}

__device__ __forceinline__ unsigned pack_h2(float lo, float hi) {
    __half2 h = __floats2half2_rn(lo, hi);
    return *(unsigned*)&h;
}

__device__ __forceinline__ uint32_t smem_u32(const void* p) {
    uint32_t a;
    asm("{ .reg .u64 t; cvta.to.shared.u64 t, %1; cvt.u32.u64 %0, t; }"
        : "=r"(a) : "l"(p));
    return a;
}

#define CP_ASYNC16(dst, src) \
    asm volatile("cp.async.cg.shared.global [%0], [%1], 16;" \
                 :: "r"(dst), "l"(src) : "memory")
#define CP_COMMIT() asm volatile("cp.async.commit_group;" ::: "memory")
#define CP_WAIT(n)  asm volatile("cp.async.wait_group %0;" :: "n"(n) : "memory")

#define LDMATRIX_X4_TRANS(r0, r1, r2, r3, addr) \
    asm volatile("ldmatrix.sync.aligned.m8n8.x4.trans.shared.b16 {%0,%1,%2,%3}, [%4];" \
                 : "=r"(r0), "=r"(r1), "=r"(r2), "=r"(r3) : "r"(addr))

// ---------------------------------------------------------------------------
// Prep kernels: fp32 -> fp16 (round-to-nearest)
// ---------------------------------------------------------------------------
__global__ void to_fp16_kernel(const float* __restrict__ src,
                               __half* __restrict__ dst, int n8)
{
    int i = blockIdx.x * blockDim.x + threadIdx.x;
    if (i >= n8) return;
    float4 a = ((const float4*)src)[2 * i];
    float4 b = ((const float4*)src)[2 * i + 1];
    uint4 o;
    o.x = pack_h2(a.x, a.y);
    o.y = pack_h2(a.z, a.w);
    o.z = pack_h2(b.x, b.y);
    o.w = pack_h2(b.z, b.w);
    ((uint4*)dst)[i] = o;
}

// dst[C][R] = fp16(src[R][C]^T)
__global__ void transpose_fp16_kernel(const float* __restrict__ src,
                                      __half* __restrict__ dst, int R, int C)
{
    __shared__ float t[32][33];
    const int bx = blockIdx.x * 32;
    const int by = blockIdx.y * 32;
    const int x = threadIdx.x, y = threadIdx.y;
#pragma unroll
    for (int j = y; j < 32; j += 8)
        t[j][x] = src[(size_t)(by + j) * C + bx + x];
    __syncthreads();
#pragma unroll
    for (int j = y; j < 32; j += 8)
        dst[(size_t)(bx + j) * R + by + x] = __float2half_rn(t[x][j]);
}

// ---------------------------------------------------------------------------
// FP16 GEMM, BK=64 halves, 2-stage double-buffered cp.async.
// 128 threads, 4 warps of 64x64, per-ks scalar LDS fragment loads.
// smem row: 32 b32 data words + 4 pad = 36 words (144B); fragment LDS banks
// (4g+tg) mod 32 all distinct -> conflict-free.
// 16 k-tiles (vs 32): half the barriers, 128-HMMA bursts per warp per tile.
// ---------------------------------------------------------------------------
#define GSTR 36
#define GTILE (128 * GSTR)                  // 4608 words per matrix per stage
#define GEMM_SMEM (2 * 2 * GTILE * 4)       // 73728 bytes

template<bool SPLIT3>
__global__ __launch_bounds__(128, 2)
void gemm_fp16_kernel(const __half* __restrict__ A,
                      const __half* __restrict__ Bt,
                      const float* __restrict__ bias,
                      float* __restrict__ C0,
                      float* __restrict__ C1,
                      float* __restrict__ C2,
                      __half* __restrict__ H0,
                      __half* __restrict__ H1,
                      __half* __restrict__ H2,
                      int M, int N, int K)
{
    extern __shared__ unsigned smw[];
    const int tid  = threadIdx.x;
    const int warp = tid >> 5;
    const int lane = tid & 31;
    const int g    = lane >> 2;
    const int tg   = lane & 3;
    const int row0 = blockIdx.y * 128;
    const int col0 = blockIdx.x * 128;
    const int wm   = (warp >> 1) * 64;
    const int wn   = (warp & 1) * 64;

    // staging: 1024 16B chunks per matrix per tile; 8 per thread
    auto issue = [&](int kt, int s) {
        const int k0 = kt * 64;
        unsigned* As = &smw[s * 2 * GTILE];
        unsigned* Bs = As + GTILE;
#pragma unroll
        for (int p = 0; p < 8; p++) {
            const int idx = tid + p * 128;          // 0..1023
            const int r = idx >> 3, ch = idx & 7;
            CP_ASYNC16(smem_u32(&As[r * GSTR + ch * 4]),
                       &A[(size_t)(row0 + r) * K + k0 + ch * 8]);
            CP_ASYNC16(smem_u32(&Bs[r * GSTR + ch * 4]),
                       &Bt[(size_t)(col0 + r) * K + k0 + ch * 8]);
        }
    };

    float acc[4][8][4];
#pragma unroll
    for (int mt = 0; mt < 4; mt++)
#pragma unroll
        for (int nt = 0; nt < 8; nt++)
#pragma unroll
            for (int i = 0; i < 4; i++) acc[mt][nt][i] = 0.0f;

    const int ksteps = K / 64;                      // 16
    issue(0, 0); CP_COMMIT();
    issue(1, 1); CP_COMMIT();

    for (int kt = 0; kt < ksteps; kt++) {
        const int s = kt & 1;
        if (kt + 1 < ksteps) { CP_WAIT(1); } else { CP_WAIT(0); }
        __syncthreads();

        const unsigned* As = &smw[s * 2 * GTILE];
        const unsigned* Bs = As + GTILE;
#pragma unroll
        for (int ks = 0; ks < 4; ks++) {            // 4 m16n8k16 steps
            unsigned af[4][4];
#pragma unroll
            for (int mt = 0; mt < 4; mt++) {
                const int r = wm + mt * 16 + g;
                const int c = ks * 8 + tg;
                af[mt][0] = As[r * GSTR + c];
                af[mt][1] = As[(r + 8) * GSTR + c];
                af[mt][2] = As[r * GSTR + c + 4];
                af[mt][3] = As[(r + 8) * GSTR + c + 4];
            }
#pragma unroll
            for (int nt = 0; nt < 8; nt++) {
                unsigned bf[2];
                const int r = wn + nt * 8 + g;
                const int c = ks * 8 + tg;
                bf[0] = Bs[r * GSTR + c];
                bf[1] = Bs[r * GSTR + c + 4];
#pragma unroll
                for (int mt = 0; mt < 4; mt++)
                    mma_fp16(acc[mt][nt], af[mt], bf);
            }
        }
        __syncthreads();                            // all reads of stage s done
        if (kt + 2 < ksteps) { issue(kt + 2, s); CP_COMMIT(); }
    }

    // epilogue
    int seg = 0, ccol0 = col0, ldc = N;
    if (SPLIT3) {
        seg   = col0 >> 10;
        ccol0 = col0 - (seg << 10);
        ldc   = EE;
    }

#pragma unroll
    for (int mt = 0; mt < 4; mt++) {
        const int r0 = row0 + wm + mt * 16 + g;
#pragma unroll
        for (int nt = 0; nt < 8; nt++) {
            const int cg = col0 + wn + nt * 8 + 2 * tg;
            const int cs = ccol0 + wn + nt * 8 + 2 * tg;
            float2 bz = *(const float2*)&bias[cg];
            float v00 = acc[mt][nt][0] + bz.x, v01 = acc[mt][nt][1] + bz.y;
            float v10 = acc[mt][nt][2] + bz.x, v11 = acc[mt][nt][3] + bz.y;
            if (SPLIT3) {
                if (seg == 0) {
                    *(unsigned*)&H0[(size_t)r0 * EE + cs] =
                        pack_h2(v00 * 0.125f, v01 * 0.125f);
                    *(unsigned*)&H0[(size_t)(r0 + 8) * EE + cs] =
                        pack_h2(v10 * 0.125f, v11 * 0.125f);
                } else {
                    float* Cf = (seg == 1) ? C1 : C2;
                    __half* Hf = (seg == 1) ? H1 : H2;
                    *(float2*)&Cf[(size_t)r0 * EE + cs]       = make_float2(v00, v01);
                    *(float2*)&Cf[(size_t)(r0 + 8) * EE + cs] = make_float2(v10, v11);
                    *(unsigned*)&Hf[(size_t)r0 * EE + cs]       = pack_h2(v00, v01);
                    *(unsigned*)&Hf[(size_t)(r0 + 8) * EE + cs] = pack_h2(v10, v11);
                }
            } else {
                *(float2*)&C0[(size_t)r0 * ldc + cs]       = make_float2(v00, v01);
                *(float2*)&C0[(size_t)(r0 + 8) * ldc + cs] = make_float2(v10, v11);
            }
        }
    }
}

// ---------------------------------------------------------------------------
// FP16 flash attention (round-11 form, measured best, byte-identical):
// P-in-register, fixed-shift softmax (C=4, P scaled x32, fp32 bias),
// 128 threads (4 warps x 32 q-rows), q-tile 128, k-tile 64, double buffer.
// smem words: K[2][64*36] | V[2][64*36] | Q[128*36]
// ---------------------------------------------------------------------------
#define ASTR 36
#define KBUF (64 * ASTR)
#define VBUF (64 * ASTR)
#define SMA_K 0
#define SMA_V (2 * KBUF)
#define SMA_Q (SMA_V + 2 * VBUF)
#define ATTN_SMEM ((SMA_Q + 128 * ASTR) * 4)   // 55296 bytes
#define SOFTMAX_C 4.0f
#define PSCALE 32.0f

__global__ __launch_bounds__(128, 2)
void flash_attn_fp16_kernel(const __half* __restrict__ qsrc,
                            const __half* __restrict__ ksrc,
                            const __half* __restrict__ vsrc,
                            const float* __restrict__ bias,
                            __half* __restrict__ ctx)
{
    extern __shared__ unsigned smw[];

    const int qb   = gridDim.x - 1 - blockIdx.x;   // largest tiles first
    const int h    = blockIdx.y;
    const int b    = blockIdx.z;
    const int tid  = threadIdx.x;
    const int warp = tid >> 5;
    const int lane = tid & 31;
    const int g    = lane >> 2;
    const int tg   = lane & 3;
    const int w32  = warp * 32;

    const int tok0 = b * SS;

    auto issue_kv = [&](int kb, int buf) {
#pragma unroll
        for (int p = 0; p < 4; p++) {
            const int idx = tid + p * 128;
            const int r = idx >> 3, ch = idx & 7;
            const size_t gi = (size_t)(tok0 + kb * 64 + r) * EE + h * DH + ch * 8;
            CP_ASYNC16(smem_u32(&smw[SMA_K + buf * KBUF + r * ASTR + ch * 4]), &ksrc[gi]);
            CP_ASYNC16(smem_u32(&smw[SMA_V + buf * VBUF + r * ASTR + ch * 4]), &vsrc[gi]);
        }
    };

    // prologue: Q tile + KV tile 0 in group 0
#pragma unroll
    for (int p = 0; p < 8; p++) {
        const int idx = tid + p * 128;
        const int r = idx >> 3, ch = idx & 7;
        CP_ASYNC16(smem_u32(&smw[SMA_Q + r * ASTR + ch * 4]),
                   &qsrc[(size_t)(tok0 + qb * 128 + r) * EE + h * DH + ch * 8]);
    }
    issue_kv(0, 0);
    CP_COMMIT();

    unsigned qa[4][2][4];               // [ks][mt][frag]
    float out[2][8][4];
    float rs[2][2];
#pragma unroll
    for (int mt = 0; mt < 2; mt++) {
        rs[mt][0] = 0.0f; rs[mt][1] = 0.0f;
#pragma unroll
        for (int nt = 0; nt < 8; nt++)
#pragma unroll
            for (int i = 0; i < 4; i++) out[mt][nt][i] = 0.0f;
    }

    int qg[2][2];
#pragma unroll
    for (int mt = 0; mt < 2; mt++) {
        qg[mt][0] = qb * 128 + w32 + mt * 16 + g;
        qg[mt][1] = qg[mt][0] + 8;
    }
    const int nkb = 2 * qb + 2;

    for (int kb = 0; kb < nkb; kb++) {
        const int buf = kb & 1;
        if (kb + 1 < nkb) { issue_kv(kb + 1, (kb + 1) & 1); CP_COMMIT(); CP_WAIT(1); }
        else              { CP_WAIT(0); }
        __syncthreads();

        if (kb == 0) {
            // Q fragments to registers (scalar LDS)
#pragma unroll
            for (int ks = 0; ks < 4; ks++)
#pragma unroll
                for (int mt = 0; mt < 2; mt++) {
                    const int r = w32 + mt * 16 + g;
                    qa[ks][mt][0] = smw[SMA_Q + r * ASTR + ks * 8 + tg];
                    qa[ks][mt][1] = smw[SMA_Q + (r + 8) * ASTR + ks * 8 + tg];
                    qa[ks][mt][2] = smw[SMA_Q + r * ASTR + ks * 8 + tg + 4];
                    qa[ks][mt][3] = smw[SMA_Q + (r + 8) * ASTR + ks * 8 + tg + 4];
                }
        }

        const unsigned* Ks = &smw[SMA_K + buf * KBUF];
        const uint32_t  Vbase = smem_u32(&smw[SMA_V + buf * VBUF]);

        // S = Q K^T  (32x64 per warp)
        float s[2][8][4];
#pragma unroll
        for (int mt = 0; mt < 2; mt++)
#pragma unroll
            for (int nt = 0; nt < 8; nt++)
#pragma unroll
                for (int i = 0; i < 4; i++) s[mt][nt][i] = 0.0f;
#pragma unroll
        for (int ks = 0; ks < 4; ks++) {
#pragma unroll
            for (int nt = 0; nt < 8; nt++) {
                unsigned bf[2];
                bf[0] = Ks[(nt * 8 + g) * ASTR + ks * 8 + tg];
                bf[1] = Ks[(nt * 8 + g) * ASTR + ks * 8 + tg + 4];
                mma_fp16(s[0][nt], qa[ks][0], bf);
                mma_fp16(s[1][nt], qa[ks][1], bf);
            }
        }

        // fused softmax epilogue + PV, one k-step (16 keys) at a time.
        const bool need_mask = (kb * 64 + 63) > qg[0][0];
#pragma unroll
        for (int ks = 0; ks < 4; ks++) {
            unsigned pa[2][4];
#pragma unroll
            for (int mt = 0; mt < 2; mt++) {
#pragma unroll
                for (int j = 0; j < 2; j++) {
                    const int nt = 2 * ks + j;
                    const int kg = kb * 64 + nt * 8 + 2 * tg;
                    float2 bz0 = *(const float2*)&bias[(size_t)qg[mt][0] * SS + kg];
                    float2 bz1 = *(const float2*)&bias[(size_t)qg[mt][1] * SS + kg];
                    float v0 = s[mt][nt][0] + bz0.x - SOFTMAX_C;
                    float v1 = s[mt][nt][1] + bz0.y - SOFTMAX_C;
                    float v2 = s[mt][nt][2] + bz1.x - SOFTMAX_C;
                    float v3 = s[mt][nt][3] + bz1.y - SOFTMAX_C;
                    if (need_mask) {
                        if (kg     > qg[mt][0]) v0 = -1e9f;
                        if (kg + 1 > qg[mt][0]) v1 = -1e9f;
                        if (kg     > qg[mt][1]) v2 = -1e9f;
                        if (kg + 1 > qg[mt][1]) v3 = -1e9f;
                    }
                    float p0 = __expf(v0) * PSCALE, p1 = __expf(v1) * PSCALE;
                    float p2 = __expf(v2) * PSCALE, p3 = __expf(v3) * PSCALE;
                    rs[mt][0] += p0 + p1;
                    rs[mt][1] += p2 + p3;
                    pa[mt][2 * j]     = pack_h2(p0, p1);
                    pa[mt][2 * j + 1] = pack_h2(p2, p3);
                }
            }
            // out += P V for this 16-key step (V via ldmatrix.trans)
#pragma unroll
            for (int np = 0; np < 4; np++) {
                const int krow = ks * 16 + (lane & 7) + ((lane >> 3) & 1) * 8;
                const int dcol = np * 16 + (lane >> 4) * 8;
                uint32_t addr = Vbase + (krow * ASTR) * 4 + dcol * 2;
                unsigned r0, r1, r2, r3;
                LDMATRIX_X4_TRANS(r0, r1, r2, r3, addr);
                unsigned bf0[2] = {r0, r1};
                unsigned bf1[2] = {r2, r3};
                mma_fp16(out[0][2 * np],     pa[0], bf0);
                mma_fp16(out[1][2 * np],     pa[1], bf0);
                mma_fp16(out[0][2 * np + 1], pa[0], bf1);
                mma_fp16(out[1][2 * np + 1], pa[1], bf1);
            }
        }
        __syncthreads();   // protect K/V buffers before re-issue
    }

    // final row-sum reduction across the tg quad
#pragma unroll
    for (int mt = 0; mt < 2; mt++)
#pragma unroll
        for (int j = 0; j < 2; j++) {
            rs[mt][j] += __shfl_xor_sync(0xffffffffu, rs[mt][j], 1);
            rs[mt][j] += __shfl_xor_sync(0xffffffffu, rs[mt][j], 2);
        }

    // write ctx fp16 (feeds proj GEMM)
#pragma unroll
    for (int mt = 0; mt < 2; mt++) {
        const float il0 = 1.0f / rs[mt][0], il1 = 1.0f / rs[mt][1];
        const int trow = tok0 + qb * 128 + w32 + mt * 16 + g;
#pragma unroll
        for (int nt = 0; nt < 8; nt++) {
            const int c = h * DH + nt * 8 + 2 * tg;
            *(unsigned*)&ctx[(size_t)trow * EE + c] =
                pack_h2(out[mt][nt][0] * il0, out[mt][nt][1] * il0);
            *(unsigned*)&ctx[(size_t)(trow + 8) * EE + c] =
                pack_h2(out[mt][nt][2] * il1, out[mt][nt][3] * il1);
        }
    }
}

// ---------------------------------------------------------------------------
// kernel_launch
// ---------------------------------------------------------------------------
extern "C" void kernel_launch(void* const* d_in, const int* in_sizes, int n_in,
                              void* d_out, int out_size)
{
    const float* hidden = (const float*)d_in[0];
    const float* bias   = (const float*)d_in[1];
    const float* Wqkv   = (const float*)d_in[2];
    const float* bqkv   = (const float*)d_in[3];
    const float* Wproj  = (const float*)d_in[4];
    const float* bproj  = (const float*)d_in[5];
    float* out = (float*)d_out;

    __half *ah, *wqkvh, *wprojh, *qh, *kh, *vh, *ctxh;
    cudaGetSymbolAddress((void**)&ah, g_ah);
    cudaGetSymbolAddress((void**)&wqkvh, g_wqkvh);
    cudaGetSymbolAddress((void**)&wprojh, g_wprojh);
    cudaGetSymbolAddress((void**)&qh, g_qh);
    cudaGetSymbolAddress((void**)&kh, g_kh);
    cudaGetSymbolAddress((void**)&vh, g_vh);
    cudaGetSymbolAddress((void**)&ctxh, g_ctxh);

    float* out_attn = out;
    float* out_key  = out + (size_t)M_TOK * EE;
    float* out_val  = out + (size_t)2 * M_TOK * EE;

    cudaFuncSetAttribute(flash_attn_fp16_kernel,
                         cudaFuncAttributeMaxDynamicSharedMemorySize, ATTN_SMEM);
    cudaFuncSetAttribute(gemm_fp16_kernel<true>,
                         cudaFuncAttributeMaxDynamicSharedMemorySize, GEMM_SMEM);
    cudaFuncSetAttribute(gemm_fp16_kernel<false>,
                         cudaFuncAttributeMaxDynamicSharedMemorySize, GEMM_SMEM);

    // 0) prep: convert hidden + transposed weights to fp16
    to_fp16_kernel<<<(M_TOK * EE / 8 + 255) / 256, 256>>>(hidden, ah, M_TOK * EE / 8);
    {
        dim3 blk(32, 8);
        transpose_fp16_kernel<<<dim3(N_QKV / 32, EE / 32), blk>>>(Wqkv, wqkvh, EE, N_QKV);
        transpose_fp16_kernel<<<dim3(EE / 32, EE / 32), blk>>>(Wproj, wprojh, EE, EE);
    }

    // 1) QKV GEMM: q -> fp16 scratch (scaled); k/v -> fp32 cache + fp16 scratch
    {
        dim3 grid(N_QKV / 128, M_TOK / 128);
        gemm_fp16_kernel<true><<<grid, 128, GEMM_SMEM>>>(
            ah, wqkvh, bqkv,
            nullptr, out_key, out_val,
            qh, kh, vh,
            M_TOK, N_QKV, EE);
    }
    // 2) attention
    {
        dim3 grid(SS / 128, HH, BB);
        flash_attn_fp16_kernel<<<grid, 128, ATTN_SMEM>>>(qh, kh, vh, bias, ctxh);
    }
    // 3) projection (fp32 output)
    {
        dim3 grid(EE / 128, M_TOK / 128);
        gemm_fp16_kernel<false><<<grid, 128, GEMM_SMEM>>>(
            ctxh, wprojh, bproj,
            out_attn, nullptr, nullptr,
            nullptr, nullptr, nullptr,
            M_TOK, EE, EE);
    }
}